// round 10
// baseline (speedup 1.0000x reference)
#include <cuda_runtime.h>
#include <cuda_bf16.h>
#include <cstdint>

// Problem constants
#define GB   2
#define GN   256
#define GL   4
#define GS   4096
#define GH   2048      // K of context GEMM
#define NH   16
#define DH   128
#define BSQ  16
#define NHD  2048
#define MM   2048      // B*N*L rows
#define KNN  4096      // [Wkc | Wvc] output cols
#define SCALE 0.08838834764831845f

// GEMM tiling: block 128x128, 4 warps (2x2), warp tile 64x64, K staged 16.
#define KC     16
#define NITER  (GH / KC)      // 128
#define ASTRIDE 20            // floats; conflict-free for the mma lane map
#define STAGE_F (128 * ASTRIDE)

// Scratch
__device__ float g_C[(size_t)MM * KNN];     // context GEMM out
__device__ float g_WT[(size_t)KNN * GH];    // W transposed [n][k], tf32-RN-rounded

// ---------------------------------------------------------------------------
// helpers
// ---------------------------------------------------------------------------
__device__ __forceinline__ uint32_t smem_u32(const void* p) {
    uint32_t a;
    asm("{ .reg .u64 t; cvta.to.shared.u64 t, %1; cvt.u32.u64 %0, t; }" : "=r"(a) : "l"(p));
    return a;
}
__device__ __forceinline__ void cp_async16(uint32_t dst, const void* src) {
    asm volatile("cp.async.cg.shared.global [%0], [%1], 16;" :: "r"(dst), "l"(src) : "memory");
}
__device__ __forceinline__ void cp_commit() {
    asm volatile("cp.async.commit_group;" ::: "memory");
}
__device__ __forceinline__ void cp_wait1() {
    asm volatile("cp.async.wait_group 1;" ::: "memory");
}
__device__ __forceinline__ uint32_t f2tf32(float f) {   // round-to-nearest tf32
    uint32_t r;
    asm("cvt.rna.tf32.f32 %0, %1;" : "=r"(r) : "f"(f));
    return r;
}
__device__ __forceinline__ void mma_tf32(float* c, const uint32_t* a, const uint32_t* b) {
    asm volatile(
        "mma.sync.aligned.m16n8k8.row.col.f32.tf32.tf32.f32 "
        "{%0,%1,%2,%3}, {%4,%5,%6,%7}, {%8,%9}, {%0,%1,%2,%3};"
        : "+f"(c[0]), "+f"(c[1]), "+f"(c[2]), "+f"(c[3])
        : "r"(a[0]), "r"(a[1]), "r"(a[2]), "r"(a[3]), "r"(b[0]), "r"(b[1]));
}

// Anchor dtype handling (harness may store int32 or int64)
__device__ __forceinline__ bool anchor_is_i64(const void* anchor) {
    const long long* a64 = (const long long*)anchor;
    bool ok = true;
    #pragma unroll
    for (int i = 0; i < 4; i++) {
        long long t = a64[i];
        if (t < 0 || t >= GS) ok = false;
    }
    return ok;
}
__device__ __forceinline__ long long anchor_read(const void* anchor, int idx, bool is64) {
    if (is64) return ((const long long*)anchor)[idx];
    return (long long)((const int*)anchor)[idx];
}

// ---------------------------------------------------------------------------
// Kernel 0: transpose [Wkc | Wvc] -> g_WT [n][k], RN-rounded to tf32.
// ---------------------------------------------------------------------------
__global__ __launch_bounds__(256) void transpose_w_kernel(
    const float* __restrict__ Wkc, const float* __restrict__ Wvc)
{
    __shared__ float t[32][33];
    const int kb = blockIdx.x * 32;
    const int nb = blockIdx.y * 32;   // global n, 0..4095
    const float* W = (nb < NHD) ? Wkc : Wvc;
    const int nloc = (nb < NHD) ? nb : nb - NHD;
    const int tx = threadIdx.x & 31, ty = threadIdx.x >> 5;
    #pragma unroll
    for (int j = 0; j < 4; j++)
        t[ty + 8 * j][tx] = W[(size_t)(kb + ty + 8 * j) * NHD + nloc + tx];
    __syncthreads();
    #pragma unroll
    for (int j = 0; j < 4; j++)
        g_WT[(size_t)(nb + ty + 8 * j) * GH + kb + tx] =
            __uint_as_float(f2tf32(t[tx][ty + 8 * j]));
}

// ---------------------------------------------------------------------------
// Kernel 1: gathered tf32 GEMM via raw mma.sync.m16n8k8 + cp.async pipeline.
//   C[m][n] = sum_k hid_gather[m][k] * g_WT[n][k]
//   Block 128x128, 4 warps, warp tile 64x64, 2-stage cp.async.
//   A fragments RN-rounded to tf32 in-register; B pre-rounded in transpose.
// ---------------------------------------------------------------------------
__global__ __launch_bounds__(128, 2) void gemm_mma_kernel(
    const float* __restrict__ hidden,
    const void* __restrict__ anchor)
{
    __shared__ __align__(16) float As[2][128][ASTRIDE];
    __shared__ __align__(16) float Bs[2][128][ASTRIDE];
    __shared__ size_t rowb[128];

    const int tid = threadIdx.x;
    const int bx = blockIdx.x;   // N tile 0..31
    const int by = blockIdx.y;   // M tile 0..15

    if (tid < 128) {
        const bool is64 = anchor_is_i64(anchor);
        int m = by * 128 + tid;
        int l = m & 3, bn = m >> 2, b = bn >> 8, n = bn & 255;
        long long a = anchor_read(anchor, b * GN + n, is64) - 1;
        if (a < 0) a = 0;
        if (a > GS - 1) a = GS - 1;
        rowb[tid] = (((size_t)l * GB + b) * GS + (size_t)a) * GH;
    }
    __syncthreads();

    const int r0 = tid >> 2;
    const int c4 = (tid & 3) << 2;
    const float* aS[4];
    const float* bS[4];
    uint32_t aD[4], bD[4];
    #pragma unroll
    for (int j = 0; j < 4; j++) {
        aS[j] = hidden + rowb[r0 + 32 * j] + c4;
        bS[j] = g_WT + (size_t)(bx * 128 + r0 + 32 * j) * GH + c4;
        aD[j] = smem_u32(&As[0][r0 + 32 * j][c4]);
        bD[j] = smem_u32(&Bs[0][r0 + 32 * j][c4]);
    }
    const uint32_t stage_b = STAGE_F * 4;

    float acc[4][8][4];
    #pragma unroll
    for (int mi = 0; mi < 4; mi++)
        #pragma unroll
        for (int ni = 0; ni < 8; ni++)
            #pragma unroll
            for (int r = 0; r < 4; r++)
                acc[mi][ni][r] = 0.0f;

    const int lane = tid & 31;
    const int warp = tid >> 5;
    const int qp = lane >> 2;
    const int qc = lane & 3;
    const int wm = warp & 1;
    const int wn = warp >> 1;

    #pragma unroll
    for (int s = 0; s < 2; s++) {
        const int k0 = s * KC;
        const uint32_t so = s * stage_b;
        #pragma unroll
        for (int j = 0; j < 4; j++) {
            cp_async16(aD[j] + so, aS[j] + k0);
            cp_async16(bD[j] + so, bS[j] + k0);
        }
        cp_commit();
    }

    for (int it = 0; it < NITER; it++) {
        cp_wait1();
        __syncthreads();

        const int buf = it & 1;
        #pragma unroll
        for (int ks = 0; ks < KC; ks += 8) {
            uint32_t a[4][4], b[8][2];
            #pragma unroll
            for (int mi = 0; mi < 4; mi++) {
                const int row = wm * 64 + mi * 16 + qp;
                a[mi][0] = f2tf32(As[buf][row][ks + qc]);
                a[mi][1] = f2tf32(As[buf][row + 8][ks + qc]);
                a[mi][2] = f2tf32(As[buf][row][ks + qc + 4]);
                a[mi][3] = f2tf32(As[buf][row + 8][ks + qc + 4]);
            }
            #pragma unroll
            for (int ni = 0; ni < 8; ni++) {
                const int rn = wn * 64 + ni * 8 + qp;
                b[ni][0] = __float_as_uint(Bs[buf][rn][ks + qc]);
                b[ni][1] = __float_as_uint(Bs[buf][rn][ks + qc + 4]);
            }
            #pragma unroll
            for (int mi = 0; mi < 4; mi++)
                #pragma unroll
                for (int ni = 0; ni < 8; ni++)
                    mma_tf32(acc[mi][ni], a[mi], b[ni]);
        }

        __syncthreads();

        const int nxt = it + 2;
        if (nxt < NITER) {
            const int k0 = nxt * KC;
            const uint32_t so = (nxt & 1) * stage_b;
            #pragma unroll
            for (int j = 0; j < 4; j++) {
                cp_async16(aD[j] + so, aS[j] + k0);
                cp_async16(bD[j] + so, bS[j] + k0);
            }
        }
        cp_commit();
    }

    #pragma unroll
    for (int mi = 0; mi < 4; mi++) {
        const int row = by * 128 + wm * 64 + mi * 16 + qp;
        #pragma unroll
        for (int ni = 0; ni < 8; ni++) {
            const int col = bx * 128 + wn * 64 + ni * 8 + 2 * qc;
            *reinterpret_cast<float2*>(&g_C[(size_t)row * KNN + col]) =
                make_float2(acc[mi][ni][0], acc[mi][ni][1]);
            *reinterpret_cast<float2*>(&g_C[(size_t)(row + 8) * KNN + col]) =
                make_float2(acc[mi][ni][2], acc[mi][ni][3]);
        }
    }
}

// ---------------------------------------------------------------------------
// Kernel 2: block-local attention, half-warp-per-query layout.
// One block per (b, n, h). 8 warps; warp w: half 0 -> query w, half 1 -> w+8.
// Lane owns d-octet; LDS.128 everywhere; 4-step half-warp reductions;
// softmax fully in-lane; float4 output stores.
// ---------------------------------------------------------------------------
__global__ __launch_bounds__(256) void attn_kernel(
    const float* __restrict__ q,
    const float* __restrict__ k,
    const float* __restrict__ v,
    const int* __restrict__ mask,
    float* __restrict__ out)
{
    const int bid = blockIdx.x;
    const int h  = bid & 15;
    const int bn = bid >> 4;
    const int n  = bn & 255;
    const int b  = bn >> 8;

    __shared__ float Qs[16][128];
    __shared__ float Ks[20][128];
    __shared__ float Vs[20][128];

    const int tid = threadIdx.x;
    const size_t qbase = ((size_t)(b * (GN * BSQ) + n * BSQ) * NH + h) * DH;

    for (int idx = tid; idx < 512; idx += 256) {
        int r = idx >> 5, c = (idx & 31) << 2;
        *reinterpret_cast<float4*>(&Qs[r][c]) =
            *reinterpret_cast<const float4*>(&q[qbase + (size_t)r * NHD + c]);
    }
    const size_t cbase = (size_t)((b * GN + n) * GL) * KNN + (size_t)h * DH;
    for (int idx = tid; idx < 640; idx += 256) {
        int r = idx >> 5, c = (idx & 31) << 2;
        float4 kv4, vv4;
        if (r < GL) {
            kv4 = *reinterpret_cast<const float4*>(&g_C[cbase + (size_t)r * KNN + c]);
            vv4 = *reinterpret_cast<const float4*>(&g_C[cbase + (size_t)r * KNN + NHD + c]);
        } else {
            size_t off = qbase + (size_t)(r - GL) * NHD + c;
            kv4 = *reinterpret_cast<const float4*>(&k[off]);
            vv4 = *reinterpret_cast<const float4*>(&v[off]);
        }
        *reinterpret_cast<float4*>(&Ks[r][c]) = kv4;
        *reinterpret_cast<float4*>(&Vs[r][c]) = vv4;
    }
    __syncthreads();

    const int lane = tid & 31;
    const int warp = tid >> 5;
    const int half = lane >> 4;          // 0 or 1
    const int hl   = lane & 15;          // lane within half
    const int qi   = warp + half * 8;    // query handled by this half-warp
    const int d0   = hl * 8;             // d-octet base
    const float keep = (mask[b * GN + n] != 0) ? 1.0f : 0.0f;

    const float4 qa = *reinterpret_cast<const float4*>(&Qs[qi][d0]);
    const float4 qb = *reinterpret_cast<const float4*>(&Qs[qi][d0 + 4]);

    float s[20];
    #pragma unroll
    for (int j = 0; j < 20; j++) {
        const float4 ka = *reinterpret_cast<const float4*>(&Ks[j][d0]);
        const float4 kb = *reinterpret_cast<const float4*>(&Ks[j][d0 + 4]);
        float acc = qa.x * ka.x + qa.y * ka.y + qa.z * ka.z + qa.w * ka.w
                  + qb.x * kb.x + qb.y * kb.y + qb.z * kb.z + qb.w * kb.w;
        #pragma unroll
        for (int o = 8; o; o >>= 1)                  // 4-step, stays in half
            acc += __shfl_xor_sync(0xffffffff, acc, o);
        s[j] = acc * SCALE;
    }

    // Softmax fully in-lane (all lanes of the half hold identical s[]).
    float mx = s[0];
    #pragma unroll
    for (int j = 1; j < 20; j++) mx = fmaxf(mx, s[j]);
    float sum = 0.0f;
    #pragma unroll
    for (int j = 0; j < 20; j++) { s[j] = __expf(s[j] - mx); sum += s[j]; }
    const float inv = keep / sum;

    float4 oa = make_float4(0.f, 0.f, 0.f, 0.f);
    float4 ob = make_float4(0.f, 0.f, 0.f, 0.f);
    #pragma unroll
    for (int j = 0; j < 20; j++) {
        const float p = s[j];
        const float4 va = *reinterpret_cast<const float4*>(&Vs[j][d0]);
        const float4 vb = *reinterpret_cast<const float4*>(&Vs[j][d0 + 4]);
        oa.x += p * va.x; oa.y += p * va.y; oa.z += p * va.z; oa.w += p * va.w;
        ob.x += p * vb.x; ob.y += p * vb.y; ob.z += p * vb.z; ob.w += p * vb.w;
    }
    oa.x *= inv; oa.y *= inv; oa.z *= inv; oa.w *= inv;
    ob.x *= inv; ob.y *= inv; ob.z *= inv; ob.w *= inv;

    const size_t obase =
        ((size_t)(b * (GN * BSQ) + n * BSQ + qi)) * NHD + (size_t)h * DH;
    *reinterpret_cast<float4*>(&out[obase + d0])     = oa;
    *reinterpret_cast<float4*>(&out[obase + d0 + 4]) = ob;
}

// ---------------------------------------------------------------------------
// kernel_launch
// ---------------------------------------------------------------------------
extern "C" void kernel_launch(void* const* d_in, const int* in_sizes, int n_in,
                              void* d_out, int out_size)
{
    const float* hidden = (const float*)d_in[0];
    const void*  anchor = d_in[1];
    const int*   mask   = (const int*)d_in[2];
    const float* q      = (const float*)d_in[3];
    const float* k      = (const float*)d_in[4];
    const float* v      = (const float*)d_in[5];
    const float* Wkc    = (const float*)d_in[6];
    const float* Wvc    = (const float*)d_in[7];

    dim3 tgrid(GH / 32, KNN / 32);   // (64, 128)
    transpose_w_kernel<<<tgrid, 256>>>(Wkc, Wvc);

    dim3 ggrid(KNN / 128, MM / 128); // (32, 16)
    gemm_mma_kernel<<<ggrid, 128>>>(hidden, anchor);

    attn_kernel<<<GB * GN * NH, 256>>>(q, k, v, mask, (float*)d_out);
}

// round 11
// speedup vs baseline: 1.1141x; 1.1141x over previous
#include <cuda_runtime.h>
#include <cuda_bf16.h>
#include <cstdint>

// Problem constants
#define GB   2
#define GN   256
#define GL   4
#define GS   4096
#define GH   2048      // K of context GEMM
#define NH   16
#define DH   128
#define BSQ  16
#define NHD  2048
#define MM   2048      // B*N*L rows
#define KNN  4096      // [Wkc | Wvc] output cols
#define SCALE 0.08838834764831845f

// GEMM tiling: block 128x128, 4 warps (2x2), warp tile 64x64, K staged 16.
#define KC     16
#define NITER  (GH / KC)      // 128
#define ASTRIDE 20            // floats; conflict-free for the mma lane map
#define STAGE_F (128 * ASTRIDE)

// Scratch
__device__ float g_C[(size_t)MM * KNN];     // context GEMM out
__device__ float g_WT[(size_t)KNN * GH];    // W transposed [n][k], tf32-RN
__device__ float g_A[(size_t)MM * GH];      // gathered hidden rows, tf32-RN

// ---------------------------------------------------------------------------
// helpers
// ---------------------------------------------------------------------------
__device__ __forceinline__ uint32_t smem_u32(const void* p) {
    uint32_t a;
    asm("{ .reg .u64 t; cvta.to.shared.u64 t, %1; cvt.u32.u64 %0, t; }" : "=r"(a) : "l"(p));
    return a;
}
__device__ __forceinline__ void cp_async16(uint32_t dst, const void* src) {
    asm volatile("cp.async.cg.shared.global [%0], [%1], 16;" :: "r"(dst), "l"(src) : "memory");
}
__device__ __forceinline__ void cp_commit() {
    asm volatile("cp.async.commit_group;" ::: "memory");
}
__device__ __forceinline__ void cp_wait1() {
    asm volatile("cp.async.wait_group 1;" ::: "memory");
}
__device__ __forceinline__ float f2tf32f(float f) {   // RN round to tf32
    uint32_t r;
    asm("cvt.rna.tf32.f32 %0, %1;" : "=r"(r) : "f"(f));
    return __uint_as_float(r);
}
__device__ __forceinline__ void mma_tf32(float* c, const uint32_t* a, const uint32_t* b) {
    asm volatile(
        "mma.sync.aligned.m16n8k8.row.col.f32.tf32.tf32.f32 "
        "{%0,%1,%2,%3}, {%4,%5,%6,%7}, {%8,%9}, {%0,%1,%2,%3};"
        : "+f"(c[0]), "+f"(c[1]), "+f"(c[2]), "+f"(c[3])
        : "r"(a[0]), "r"(a[1]), "r"(a[2]), "r"(a[3]), "r"(b[0]), "r"(b[1]));
}

// Anchor dtype handling (harness may store int32 or int64)
__device__ __forceinline__ bool anchor_is_i64(const void* anchor) {
    const long long* a64 = (const long long*)anchor;
    bool ok = true;
    #pragma unroll
    for (int i = 0; i < 4; i++) {
        long long t = a64[i];
        if (t < 0 || t >= GS) ok = false;
    }
    return ok;
}
__device__ __forceinline__ long long anchor_read(const void* anchor, int idx, bool is64) {
    if (is64) return ((const long long*)anchor)[idx];
    return (long long)((const int*)anchor)[idx];
}

// ---------------------------------------------------------------------------
// Kernel 0a: gather + RN-round A rows.  g_A[m][k] = rn(hidden[ctx(m)][k])
// ---------------------------------------------------------------------------
__global__ __launch_bounds__(256) void gather_a_kernel(
    const float* __restrict__ hidden, const void* __restrict__ anchor)
{
    const int m = blockIdx.x;
    const int l = m & 3, bn = m >> 2, b = bn >> 8, n = bn & 255;
    const bool is64 = anchor_is_i64(anchor);
    long long a = anchor_read(anchor, b * GN + n, is64) - 1;
    if (a < 0) a = 0;
    if (a > GS - 1) a = GS - 1;
    const float* src = hidden + (((size_t)l * GB + b) * GS + (size_t)a) * GH;
    float* dst = g_A + (size_t)m * GH;
    #pragma unroll
    for (int c = threadIdx.x * 4; c < GH; c += 256 * 4) {
        float4 v = *reinterpret_cast<const float4*>(src + c);
        v.x = f2tf32f(v.x); v.y = f2tf32f(v.y);
        v.z = f2tf32f(v.z); v.w = f2tf32f(v.w);
        *reinterpret_cast<float4*>(dst + c) = v;
    }
}

// ---------------------------------------------------------------------------
// Kernel 0b: transpose [Wkc | Wvc] -> g_WT [n][k], RN-rounded to tf32.
// ---------------------------------------------------------------------------
__global__ __launch_bounds__(256) void transpose_w_kernel(
    const float* __restrict__ Wkc, const float* __restrict__ Wvc)
{
    __shared__ float t[32][33];
    const int kb = blockIdx.x * 32;
    const int nb = blockIdx.y * 32;   // global n, 0..4095
    const float* W = (nb < NHD) ? Wkc : Wvc;
    const int nloc = (nb < NHD) ? nb : nb - NHD;
    const int tx = threadIdx.x & 31, ty = threadIdx.x >> 5;
    #pragma unroll
    for (int j = 0; j < 4; j++)
        t[ty + 8 * j][tx] = W[(size_t)(kb + ty + 8 * j) * NHD + nloc + tx];
    __syncthreads();
    #pragma unroll
    for (int j = 0; j < 4; j++)
        g_WT[(size_t)(nb + ty + 8 * j) * GH + kb + tx] = f2tf32f(t[tx][ty + 8 * j]);
}

// ---------------------------------------------------------------------------
// Kernel 1: tf32 GEMM via raw mma.sync.m16n8k8 + cp.async, both operands
// pre-rounded and coalesced (g_A, g_WT). No cvt, no gather in mainloop.
// ---------------------------------------------------------------------------
__global__ __launch_bounds__(128, 2) void gemm_mma_kernel()
{
    __shared__ __align__(16) float As[2][128][ASTRIDE];
    __shared__ __align__(16) float Bs[2][128][ASTRIDE];

    const int tid = threadIdx.x;
    const int bx = blockIdx.x;   // N tile 0..31
    const int by = blockIdx.y;   // M tile 0..15

    const int r0 = tid >> 2;
    const int c4 = (tid & 3) << 2;
    const float* aS[4];
    const float* bS[4];
    uint32_t aD[4], bD[4];
    #pragma unroll
    for (int j = 0; j < 4; j++) {
        aS[j] = g_A + (size_t)(by * 128 + r0 + 32 * j) * GH + c4;
        bS[j] = g_WT + (size_t)(bx * 128 + r0 + 32 * j) * GH + c4;
        aD[j] = smem_u32(&As[0][r0 + 32 * j][c4]);
        bD[j] = smem_u32(&Bs[0][r0 + 32 * j][c4]);
    }
    const uint32_t stage_b = STAGE_F * 4;

    float acc[4][8][4];
    #pragma unroll
    for (int mi = 0; mi < 4; mi++)
        #pragma unroll
        for (int ni = 0; ni < 8; ni++)
            #pragma unroll
            for (int r = 0; r < 4; r++)
                acc[mi][ni][r] = 0.0f;

    const int lane = tid & 31;
    const int warp = tid >> 5;
    const int qp = lane >> 2;
    const int qc = lane & 3;
    const int wm = warp & 1;
    const int wn = warp >> 1;

    #pragma unroll
    for (int s = 0; s < 2; s++) {
        const int k0 = s * KC;
        const uint32_t so = s * stage_b;
        #pragma unroll
        for (int j = 0; j < 4; j++) {
            cp_async16(aD[j] + so, aS[j] + k0);
            cp_async16(bD[j] + so, bS[j] + k0);
        }
        cp_commit();
    }

    for (int it = 0; it < NITER; it++) {
        cp_wait1();
        __syncthreads();

        const int buf = it & 1;
        #pragma unroll
        for (int ks = 0; ks < KC; ks += 8) {
            uint32_t a[4][4], b[8][2];
            #pragma unroll
            for (int mi = 0; mi < 4; mi++) {
                const int row = wm * 64 + mi * 16 + qp;
                a[mi][0] = __float_as_uint(As[buf][row][ks + qc]);
                a[mi][1] = __float_as_uint(As[buf][row + 8][ks + qc]);
                a[mi][2] = __float_as_uint(As[buf][row][ks + qc + 4]);
                a[mi][3] = __float_as_uint(As[buf][row + 8][ks + qc + 4]);
            }
            #pragma unroll
            for (int ni = 0; ni < 8; ni++) {
                const int rn = wn * 64 + ni * 8 + qp;
                b[ni][0] = __float_as_uint(Bs[buf][rn][ks + qc]);
                b[ni][1] = __float_as_uint(Bs[buf][rn][ks + qc + 4]);
            }
            #pragma unroll
            for (int mi = 0; mi < 4; mi++)
                #pragma unroll
                for (int ni = 0; ni < 8; ni++)
                    mma_tf32(acc[mi][ni], a[mi], b[ni]);
        }

        __syncthreads();

        const int nxt = it + 2;
        if (nxt < NITER) {
            const int k0 = nxt * KC;
            const uint32_t so = (nxt & 1) * stage_b;
            #pragma unroll
            for (int j = 0; j < 4; j++) {
                cp_async16(aD[j] + so, aS[j] + k0);
                cp_async16(bD[j] + so, bS[j] + k0);
            }
        }
        cp_commit();
    }

    #pragma unroll
    for (int mi = 0; mi < 4; mi++) {
        const int row = by * 128 + wm * 64 + mi * 16 + qp;
        #pragma unroll
        for (int ni = 0; ni < 8; ni++) {
            const int col = bx * 128 + wn * 64 + ni * 8 + 2 * qc;
            *reinterpret_cast<float2*>(&g_C[(size_t)row * KNN + col]) =
                make_float2(acc[mi][ni][0], acc[mi][ni][1]);
            *reinterpret_cast<float2*>(&g_C[(size_t)(row + 8) * KNN + col]) =
                make_float2(acc[mi][ni][2], acc[mi][ni][3]);
        }
    }
}

// ---------------------------------------------------------------------------
// Kernel 2: block-local attention, half-warp-per-query, CONFLICT-FREE chunks.
// Lane hl owns float4 chunks at d = hl*4 and d = 64 + hl*4 (per 8-lane LDS
// phase, banks hl*4 mod 32 are all-distinct -> no conflicts).
// ---------------------------------------------------------------------------
__global__ __launch_bounds__(256) void attn_kernel(
    const float* __restrict__ q,
    const float* __restrict__ k,
    const float* __restrict__ v,
    const int* __restrict__ mask,
    float* __restrict__ out)
{
    const int bid = blockIdx.x;
    const int h  = bid & 15;
    const int bn = bid >> 4;
    const int n  = bn & 255;
    const int b  = bn >> 8;

    __shared__ float Qs[16][128];
    __shared__ float Ks[20][128];
    __shared__ float Vs[20][128];

    const int tid = threadIdx.x;
    const size_t qbase = ((size_t)(b * (GN * BSQ) + n * BSQ) * NH + h) * DH;

    for (int idx = tid; idx < 512; idx += 256) {
        int r = idx >> 5, c = (idx & 31) << 2;
        *reinterpret_cast<float4*>(&Qs[r][c]) =
            *reinterpret_cast<const float4*>(&q[qbase + (size_t)r * NHD + c]);
    }
    const size_t cbase = (size_t)((b * GN + n) * GL) * KNN + (size_t)h * DH;
    for (int idx = tid; idx < 640; idx += 256) {
        int r = idx >> 5, c = (idx & 31) << 2;
        float4 kv4, vv4;
        if (r < GL) {
            kv4 = *reinterpret_cast<const float4*>(&g_C[cbase + (size_t)r * KNN + c]);
            vv4 = *reinterpret_cast<const float4*>(&g_C[cbase + (size_t)r * KNN + NHD + c]);
        } else {
            size_t off = qbase + (size_t)(r - GL) * NHD + c;
            kv4 = *reinterpret_cast<const float4*>(&k[off]);
            vv4 = *reinterpret_cast<const float4*>(&v[off]);
        }
        *reinterpret_cast<float4*>(&Ks[r][c]) = kv4;
        *reinterpret_cast<float4*>(&Vs[r][c]) = vv4;
    }
    __syncthreads();

    const int lane = tid & 31;
    const int warp = tid >> 5;
    const int half = lane >> 4;          // 0 or 1
    const int hl   = lane & 15;          // lane within half
    const int qi   = warp + half * 8;    // query handled by this half-warp
    const int c0   = hl * 4;             // first chunk
    const int c1   = 64 + hl * 4;        // second chunk
    const float keep = (mask[b * GN + n] != 0) ? 1.0f : 0.0f;

    const float4 qa = *reinterpret_cast<const float4*>(&Qs[qi][c0]);
    const float4 qb = *reinterpret_cast<const float4*>(&Qs[qi][c1]);

    float s[20];
    #pragma unroll
    for (int j = 0; j < 20; j++) {
        const float4 ka = *reinterpret_cast<const float4*>(&Ks[j][c0]);
        const float4 kb = *reinterpret_cast<const float4*>(&Ks[j][c1]);
        float acc = qa.x * ka.x + qa.y * ka.y + qa.z * ka.z + qa.w * ka.w
                  + qb.x * kb.x + qb.y * kb.y + qb.z * kb.z + qb.w * kb.w;
        #pragma unroll
        for (int o = 8; o; o >>= 1)                  // 4-step, stays in half
            acc += __shfl_xor_sync(0xffffffff, acc, o);
        s[j] = acc * SCALE;
    }

    float mx = s[0];
    #pragma unroll
    for (int j = 1; j < 20; j++) mx = fmaxf(mx, s[j]);
    float sum = 0.0f;
    #pragma unroll
    for (int j = 0; j < 20; j++) { s[j] = __expf(s[j] - mx); sum += s[j]; }
    const float inv = keep / sum;

    float4 oa = make_float4(0.f, 0.f, 0.f, 0.f);
    float4 ob = make_float4(0.f, 0.f, 0.f, 0.f);
    #pragma unroll
    for (int j = 0; j < 20; j++) {
        const float p = s[j];
        const float4 va = *reinterpret_cast<const float4*>(&Vs[j][c0]);
        const float4 vb = *reinterpret_cast<const float4*>(&Vs[j][c1]);
        oa.x += p * va.x; oa.y += p * va.y; oa.z += p * va.z; oa.w += p * va.w;
        ob.x += p * vb.x; ob.y += p * vb.y; ob.z += p * vb.z; ob.w += p * vb.w;
    }
    oa.x *= inv; oa.y *= inv; oa.z *= inv; oa.w *= inv;
    ob.x *= inv; ob.y *= inv; ob.z *= inv; ob.w *= inv;

    const size_t obase =
        ((size_t)(b * (GN * BSQ) + n * BSQ + qi)) * NHD + (size_t)h * DH;
    *reinterpret_cast<float4*>(&out[obase + c0]) = oa;
    *reinterpret_cast<float4*>(&out[obase + c1]) = ob;
}

// ---------------------------------------------------------------------------
// kernel_launch
// ---------------------------------------------------------------------------
extern "C" void kernel_launch(void* const* d_in, const int* in_sizes, int n_in,
                              void* d_out, int out_size)
{
    const float* hidden = (const float*)d_in[0];
    const void*  anchor = d_in[1];
    const int*   mask   = (const int*)d_in[2];
    const float* q      = (const float*)d_in[3];
    const float* k      = (const float*)d_in[4];
    const float* v      = (const float*)d_in[5];
    const float* Wkc    = (const float*)d_in[6];
    const float* Wvc    = (const float*)d_in[7];

    gather_a_kernel<<<MM, 256>>>(hidden, anchor);

    dim3 tgrid(GH / 32, KNN / 32);   // (64, 128)
    transpose_w_kernel<<<tgrid, 256>>>(Wkc, Wvc);

    dim3 ggrid(KNN / 128, MM / 128); // (32, 16)
    gemm_mma_kernel<<<ggrid, 128>>>();

    attn_kernel<<<GB * GN * NH, 256>>>(q, k, v, mask, (float*)d_out);
}

// round 12
// speedup vs baseline: 1.6507x; 1.4817x over previous
#include <cuda_runtime.h>
#include <cuda_fp16.h>
#include <cstdint>

// Problem constants
#define GB   2
#define GN   256
#define GL   4
#define GS   4096
#define GH   2048      // K of context GEMM
#define NH   16
#define DH   128
#define BSQ  16
#define NHD  2048
#define MM   2048      // B*N*L rows
#define KNN  4096      // [Wkc | Wvc] output cols
#define SCALE 0.08838834764831845f

// GEMM tiling: block 128x128, 4 warps (2x2), warp tile 64x64.
// fp16 path: K staged 32 halves (64 B/row), m16n8k16.
#define KC     32                 // halves per stage
#define NITER  (GH / KC)          // 64
#define AWORDS 20                 // uint32 words per smem row (16 data + 4 pad)
#define STAGE_W (128 * AWORDS)    // words per stage per operand

// Scratch
__device__ float  g_C[(size_t)MM * KNN];     // context GEMM out (fp32)
__device__ __half g_WTh[(size_t)KNN * GH];   // W transposed [n][k], fp16
__device__ __half g_Ah[(size_t)MM * GH];     // gathered hidden rows, fp16

// ---------------------------------------------------------------------------
// helpers
// ---------------------------------------------------------------------------
__device__ __forceinline__ uint32_t smem_u32(const void* p) {
    uint32_t a;
    asm("{ .reg .u64 t; cvta.to.shared.u64 t, %1; cvt.u32.u64 %0, t; }" : "=r"(a) : "l"(p));
    return a;
}
__device__ __forceinline__ void cp_async16(uint32_t dst, const void* src) {
    asm volatile("cp.async.cg.shared.global [%0], [%1], 16;" :: "r"(dst), "l"(src) : "memory");
}
__device__ __forceinline__ void cp_commit() {
    asm volatile("cp.async.commit_group;" ::: "memory");
}
__device__ __forceinline__ void cp_wait1() {
    asm volatile("cp.async.wait_group 1;" ::: "memory");
}
__device__ __forceinline__ void mma_fp16(float* c, const uint32_t* a, const uint32_t* b) {
    asm volatile(
        "mma.sync.aligned.m16n8k16.row.col.f32.f16.f16.f32 "
        "{%0,%1,%2,%3}, {%4,%5,%6,%7}, {%8,%9}, {%0,%1,%2,%3};"
        : "+f"(c[0]), "+f"(c[1]), "+f"(c[2]), "+f"(c[3])
        : "r"(a[0]), "r"(a[1]), "r"(a[2]), "r"(a[3]), "r"(b[0]), "r"(b[1]));
}

// Anchor dtype handling (harness may store int32 or int64)
__device__ __forceinline__ bool anchor_is_i64(const void* anchor) {
    const long long* a64 = (const long long*)anchor;
    bool ok = true;
    #pragma unroll
    for (int i = 0; i < 4; i++) {
        long long t = a64[i];
        if (t < 0 || t >= GS) ok = false;
    }
    return ok;
}
__device__ __forceinline__ long long anchor_read(const void* anchor, int idx, bool is64) {
    if (is64) return ((const long long*)anchor)[idx];
    return (long long)((const int*)anchor)[idx];
}

// ---------------------------------------------------------------------------
// Kernel 0a: gather + fp16-convert A rows. g_Ah[m][k] = (half)hidden[ctx(m)][k]
// ---------------------------------------------------------------------------
__global__ __launch_bounds__(256) void gather_a_kernel(
    const float* __restrict__ hidden, const void* __restrict__ anchor)
{
    const int m = blockIdx.x;
    const int l = m & 3, bn = m >> 2, b = bn >> 8, n = bn & 255;
    const bool is64 = anchor_is_i64(anchor);
    long long a = anchor_read(anchor, b * GN + n, is64) - 1;
    if (a < 0) a = 0;
    if (a > GS - 1) a = GS - 1;
    const float* src = hidden + (((size_t)l * GB + b) * GS + (size_t)a) * GH;
    __half* dst = g_Ah + (size_t)m * GH;
    // 8 floats -> 8 halves (16B store) per thread; 2048/8 = 256 = blockDim.
    const int c = threadIdx.x * 8;
    float4 v0 = *reinterpret_cast<const float4*>(src + c);
    float4 v1 = *reinterpret_cast<const float4*>(src + c + 4);
    __half2 h[4];
    h[0] = __floats2half2_rn(v0.x, v0.y);
    h[1] = __floats2half2_rn(v0.z, v0.w);
    h[2] = __floats2half2_rn(v1.x, v1.y);
    h[3] = __floats2half2_rn(v1.z, v1.w);
    *reinterpret_cast<uint4*>(dst + c) = *reinterpret_cast<uint4*>(h);
}

// ---------------------------------------------------------------------------
// Kernel 0b: transpose [Wkc | Wvc] -> g_WTh [n][k], fp16.
// ---------------------------------------------------------------------------
__global__ __launch_bounds__(256) void transpose_w_kernel(
    const float* __restrict__ Wkc, const float* __restrict__ Wvc)
{
    __shared__ float t[32][33];
    const int kb = blockIdx.x * 32;
    const int nb = blockIdx.y * 32;   // global n, 0..4095
    const float* W = (nb < NHD) ? Wkc : Wvc;
    const int nloc = (nb < NHD) ? nb : nb - NHD;
    const int tx = threadIdx.x & 31, ty = threadIdx.x >> 5;
    #pragma unroll
    for (int j = 0; j < 4; j++)
        t[ty + 8 * j][tx] = W[(size_t)(kb + ty + 8 * j) * NHD + nloc + tx];
    __syncthreads();
    #pragma unroll
    for (int j = 0; j < 4; j++)
        g_WTh[(size_t)(nb + ty + 8 * j) * GH + kb + tx] = __float2half_rn(t[tx][ty + 8 * j]);
}

// ---------------------------------------------------------------------------
// Kernel 1: fp16 GEMM (fp32 accum) via mma.sync.m16n8k16 + cp.async.
//   C[m][n] = sum_k g_Ah[m][k] * g_WTh[n][k]
//   Block 128x128, 4 warps, warp tile 64x64, 2-stage, K=32 per stage.
// ---------------------------------------------------------------------------
__global__ __launch_bounds__(128, 2) void gemm_mma_kernel()
{
    __shared__ __align__(16) uint32_t As[2][128][AWORDS];
    __shared__ __align__(16) uint32_t Bs[2][128][AWORDS];

    const int tid = threadIdx.x;
    const int bx = blockIdx.x;   // N tile 0..31
    const int by = blockIdx.y;   // M tile 0..15

    // cp.async: per stage per operand 128 rows x 4 16B-chunks = 512 chunks;
    // thread handles chunk (tid&3) of rows (tid>>2) + 32j, both operands.
    const int r0 = tid >> 2;
    const int ch = tid & 3;           // chunk 0..3, 8 halves each
    const __half* aS[4];
    const __half* bS[4];
    uint32_t aD[4], bD[4];
    #pragma unroll
    for (int j = 0; j < 4; j++) {
        aS[j] = g_Ah + (size_t)(by * 128 + r0 + 32 * j) * GH + ch * 8;
        bS[j] = g_WTh + (size_t)(bx * 128 + r0 + 32 * j) * GH + ch * 8;
        aD[j] = smem_u32(&As[0][r0 + 32 * j][ch * 4]);
        bD[j] = smem_u32(&Bs[0][r0 + 32 * j][ch * 4]);
    }
    const uint32_t stage_b = STAGE_W * 4;   // bytes per stage

    float acc[4][8][4];
    #pragma unroll
    for (int mi = 0; mi < 4; mi++)
        #pragma unroll
        for (int ni = 0; ni < 8; ni++)
            #pragma unroll
            for (int r = 0; r < 4; r++)
                acc[mi][ni][r] = 0.0f;

    const int lane = tid & 31;
    const int warp = tid >> 5;
    const int qp = lane >> 2;
    const int qc = lane & 3;
    const int wm = warp & 1;
    const int wn = warp >> 1;

    #pragma unroll
    for (int s = 0; s < 2; s++) {
        const int k0 = s * KC;
        const uint32_t so = s * stage_b;
        #pragma unroll
        for (int j = 0; j < 4; j++) {
            cp_async16(aD[j] + so, aS[j] + k0);
            cp_async16(bD[j] + so, bS[j] + k0);
        }
        cp_commit();
    }

    for (int it = 0; it < NITER; it++) {
        cp_wait1();
        __syncthreads();

        const int buf = it & 1;
        #pragma unroll
        for (int step = 0; step < 2; step++) {       // 2 x k16 per stage
            const int wb = step * 8;                 // word base
            uint32_t a[4][4], b[8][2];
            #pragma unroll
            for (int mi = 0; mi < 4; mi++) {
                const int row = wm * 64 + mi * 16 + qp;
                a[mi][0] = As[buf][row][wb + qc];
                a[mi][1] = As[buf][row + 8][wb + qc];
                a[mi][2] = As[buf][row][wb + 4 + qc];
                a[mi][3] = As[buf][row + 8][wb + 4 + qc];
            }
            #pragma unroll
            for (int ni = 0; ni < 8; ni++) {
                const int rn = wn * 64 + ni * 8 + qp;
                b[ni][0] = Bs[buf][rn][wb + qc];
                b[ni][1] = Bs[buf][rn][wb + 4 + qc];
            }
            #pragma unroll
            for (int mi = 0; mi < 4; mi++)
                #pragma unroll
                for (int ni = 0; ni < 8; ni++)
                    mma_fp16(acc[mi][ni], a[mi], b[ni]);
        }

        __syncthreads();

        const int nxt = it + 2;
        if (nxt < NITER) {
            const int k0 = nxt * KC;
            const uint32_t so = (nxt & 1) * stage_b;
            #pragma unroll
            for (int j = 0; j < 4; j++) {
                cp_async16(aD[j] + so, aS[j] + k0);
                cp_async16(bD[j] + so, bS[j] + k0);
            }
        }
        cp_commit();
    }

    #pragma unroll
    for (int mi = 0; mi < 4; mi++) {
        const int row = by * 128 + wm * 64 + mi * 16 + qp;
        #pragma unroll
        for (int ni = 0; ni < 8; ni++) {
            const int col = bx * 128 + wn * 64 + ni * 8 + 2 * qc;
            *reinterpret_cast<float2*>(&g_C[(size_t)row * KNN + col]) =
                make_float2(acc[mi][ni][0], acc[mi][ni][1]);
            *reinterpret_cast<float2*>(&g_C[(size_t)(row + 8) * KNN + col]) =
                make_float2(acc[mi][ni][2], acc[mi][ni][3]);
        }
    }
}

// ---------------------------------------------------------------------------
// Kernel 2: block-local attention, half-warp-per-query, conflict-free chunks.
// (unchanged from R11)
// ---------------------------------------------------------------------------
__global__ __launch_bounds__(256) void attn_kernel(
    const float* __restrict__ q,
    const float* __restrict__ k,
    const float* __restrict__ v,
    const int* __restrict__ mask,
    float* __restrict__ out)
{
    const int bid = blockIdx.x;
    const int h  = bid & 15;
    const int bn = bid >> 4;
    const int n  = bn & 255;
    const int b  = bn >> 8;

    __shared__ float Qs[16][128];
    __shared__ float Ks[20][128];
    __shared__ float Vs[20][128];

    const int tid = threadIdx.x;
    const size_t qbase = ((size_t)(b * (GN * BSQ) + n * BSQ) * NH + h) * DH;

    for (int idx = tid; idx < 512; idx += 256) {
        int r = idx >> 5, c = (idx & 31) << 2;
        *reinterpret_cast<float4*>(&Qs[r][c]) =
            *reinterpret_cast<const float4*>(&q[qbase + (size_t)r * NHD + c]);
    }
    const size_t cbase = (size_t)((b * GN + n) * GL) * KNN + (size_t)h * DH;
    for (int idx = tid; idx < 640; idx += 256) {
        int r = idx >> 5, c = (idx & 31) << 2;
        float4 kv4, vv4;
        if (r < GL) {
            kv4 = *reinterpret_cast<const float4*>(&g_C[cbase + (size_t)r * KNN + c]);
            vv4 = *reinterpret_cast<const float4*>(&g_C[cbase + (size_t)r * KNN + NHD + c]);
        } else {
            size_t off = qbase + (size_t)(r - GL) * NHD + c;
            kv4 = *reinterpret_cast<const float4*>(&k[off]);
            vv4 = *reinterpret_cast<const float4*>(&v[off]);
        }
        *reinterpret_cast<float4*>(&Ks[r][c]) = kv4;
        *reinterpret_cast<float4*>(&Vs[r][c]) = vv4;
    }
    __syncthreads();

    const int lane = tid & 31;
    const int warp = tid >> 5;
    const int half = lane >> 4;
    const int hl   = lane & 15;
    const int qi   = warp + half * 8;
    const int c0   = hl * 4;
    const int c1   = 64 + hl * 4;
    const float keep = (mask[b * GN + n] != 0) ? 1.0f : 0.0f;

    const float4 qa = *reinterpret_cast<const float4*>(&Qs[qi][c0]);
    const float4 qb = *reinterpret_cast<const float4*>(&Qs[qi][c1]);

    float s[20];
    #pragma unroll
    for (int j = 0; j < 20; j++) {
        const float4 ka = *reinterpret_cast<const float4*>(&Ks[j][c0]);
        const float4 kb = *reinterpret_cast<const float4*>(&Ks[j][c1]);
        float acc = qa.x * ka.x + qa.y * ka.y + qa.z * ka.z + qa.w * ka.w
                  + qb.x * kb.x + qb.y * kb.y + qb.z * kb.z + qb.w * kb.w;
        #pragma unroll
        for (int o = 8; o; o >>= 1)
            acc += __shfl_xor_sync(0xffffffff, acc, o);
        s[j] = acc * SCALE;
    }

    float mx = s[0];
    #pragma unroll
    for (int j = 1; j < 20; j++) mx = fmaxf(mx, s[j]);
    float sum = 0.0f;
    #pragma unroll
    for (int j = 0; j < 20; j++) { s[j] = __expf(s[j] - mx); sum += s[j]; }
    const float inv = keep / sum;

    float4 oa = make_float4(0.f, 0.f, 0.f, 0.f);
    float4 ob = make_float4(0.f, 0.f, 0.f, 0.f);
    #pragma unroll
    for (int j = 0; j < 20; j++) {
        const float p = s[j];
        const float4 va = *reinterpret_cast<const float4*>(&Vs[j][c0]);
        const float4 vb = *reinterpret_cast<const float4*>(&Vs[j][c1]);
        oa.x += p * va.x; oa.y += p * va.y; oa.z += p * va.z; oa.w += p * va.w;
        ob.x += p * vb.x; ob.y += p * vb.y; ob.z += p * vb.z; ob.w += p * vb.w;
    }
    oa.x *= inv; oa.y *= inv; oa.z *= inv; oa.w *= inv;
    ob.x *= inv; ob.y *= inv; ob.z *= inv; ob.w *= inv;

    const size_t obase =
        ((size_t)(b * (GN * BSQ) + n * BSQ + qi)) * NHD + (size_t)h * DH;
    *reinterpret_cast<float4*>(&out[obase + c0]) = oa;
    *reinterpret_cast<float4*>(&out[obase + c1]) = ob;
}

// ---------------------------------------------------------------------------
// kernel_launch
// ---------------------------------------------------------------------------
extern "C" void kernel_launch(void* const* d_in, const int* in_sizes, int n_in,
                              void* d_out, int out_size)
{
    const float* hidden = (const float*)d_in[0];
    const void*  anchor = d_in[1];
    const int*   mask   = (const int*)d_in[2];
    const float* q      = (const float*)d_in[3];
    const float* k      = (const float*)d_in[4];
    const float* v      = (const float*)d_in[5];
    const float* Wkc    = (const float*)d_in[6];
    const float* Wvc    = (const float*)d_in[7];

    gather_a_kernel<<<MM, 256>>>(hidden, anchor);

    dim3 tgrid(GH / 32, KNN / 32);   // (64, 128)
    transpose_w_kernel<<<tgrid, 256>>>(Wkc, Wvc);

    dim3 ggrid(KNN / 128, MM / 128); // (32, 16)
    gemm_mma_kernel<<<ggrid, 128>>>();

    attn_kernel<<<GB * GN * NH, 256>>>(q, k, v, mask, (float*)d_out);
}

// round 14
// speedup vs baseline: 1.9720x; 1.1946x over previous
#include <cuda_runtime.h>
#include <cuda_fp16.h>
#include <cstdint>

// Problem constants
#define GB   2
#define GN   256
#define GL   4
#define GS   4096
#define GH   2048      // K of context GEMM
#define NH   16
#define DH   128
#define BSQ  16
#define NHD  2048
#define MM   2048      // B*N*L rows
#define KNN  4096      // [Wkc | Wvc] output cols
#define SCALE 0.08838834764831845f

// GEMM tiling
#define KC     32
#define NITER  (GH / KC)          // 64
#define AWORDS 20
#define STAGE_W (128 * AWORDS)

// Scratch
__device__ __half g_Ch[(size_t)MM * KNN];    // context GEMM out (fp16)
__device__ __half g_WTh[(size_t)KNN * GH];   // W transposed [n][k], fp16
__device__ __half g_Ah[(size_t)MM * GH];     // gathered hidden rows, fp16

// ---------------------------------------------------------------------------
// helpers
// ---------------------------------------------------------------------------
__device__ __forceinline__ uint32_t smem_u32(const void* p) {
    uint32_t a;
    asm("{ .reg .u64 t; cvta.to.shared.u64 t, %1; cvt.u32.u64 %0, t; }" : "=r"(a) : "l"(p));
    return a;
}
__device__ __forceinline__ void cp_async16(uint32_t dst, const void* src) {
    asm volatile("cp.async.cg.shared.global [%0], [%1], 16;" :: "r"(dst), "l"(src) : "memory");
}
__device__ __forceinline__ void cp_commit() {
    asm volatile("cp.async.commit_group;" ::: "memory");
}
__device__ __forceinline__ void cp_wait1() {
    asm volatile("cp.async.wait_group 1;" ::: "memory");
}
__device__ __forceinline__ void mma_fp16(float* c, const uint32_t* a, const uint32_t* b) {
    asm volatile(
        "mma.sync.aligned.m16n8k16.row.col.f32.f16.f16.f32 "
        "{%0,%1,%2,%3}, {%4,%5,%6,%7}, {%8,%9}, {%0,%1,%2,%3};"
        : "+f"(c[0]), "+f"(c[1]), "+f"(c[2]), "+f"(c[3])
        : "r"(a[0]), "r"(a[1]), "r"(a[2]), "r"(a[3]), "r"(b[0]), "r"(b[1]));
}
__device__ __forceinline__ void ldsm_x4_t(uint32_t& r0, uint32_t& r1,
                                          uint32_t& r2, uint32_t& r3, uint32_t addr) {
    asm volatile("ldmatrix.sync.aligned.m8n8.x4.trans.shared.b16 {%0,%1,%2,%3}, [%4];"
                 : "=r"(r0), "=r"(r1), "=r"(r2), "=r"(r3) : "r"(addr));
}

// Anchor dtype handling (harness may store int32 or int64)
__device__ __forceinline__ bool anchor_is_i64(const void* anchor) {
    const long long* a64 = (const long long*)anchor;
    bool ok = true;
    #pragma unroll
    for (int i = 0; i < 4; i++) {
        long long t = a64[i];
        if (t < 0 || t >= GS) ok = false;
    }
    return ok;
}
__device__ __forceinline__ long long anchor_read(const void* anchor, int idx, bool is64) {
    if (is64) return ((const long long*)anchor)[idx];
    return (long long)((const int*)anchor)[idx];
}

// ---------------------------------------------------------------------------
// Kernel 0a: gather + fp16-convert A rows
// ---------------------------------------------------------------------------
__global__ __launch_bounds__(256) void gather_a_kernel(
    const float* __restrict__ hidden, const void* __restrict__ anchor)
{
    const int m = blockIdx.x;
    const int l = m & 3, bn = m >> 2, b = bn >> 8, n = bn & 255;
    const bool is64 = anchor_is_i64(anchor);
    long long a = anchor_read(anchor, b * GN + n, is64) - 1;
    if (a < 0) a = 0;
    if (a > GS - 1) a = GS - 1;
    const float* src = hidden + (((size_t)l * GB + b) * GS + (size_t)a) * GH;
    __half* dst = g_Ah + (size_t)m * GH;
    const int c = threadIdx.x * 8;
    float4 v0 = *reinterpret_cast<const float4*>(src + c);
    float4 v1 = *reinterpret_cast<const float4*>(src + c + 4);
    __half2 h[4];
    h[0] = __floats2half2_rn(v0.x, v0.y);
    h[1] = __floats2half2_rn(v0.z, v0.w);
    h[2] = __floats2half2_rn(v1.x, v1.y);
    h[3] = __floats2half2_rn(v1.z, v1.w);
    *reinterpret_cast<uint4*>(dst + c) = *reinterpret_cast<uint4*>(h);
}

// ---------------------------------------------------------------------------
// Kernel 0b: transpose [Wkc | Wvc] -> g_WTh [n][k], fp16
// ---------------------------------------------------------------------------
__global__ __launch_bounds__(256) void transpose_w_kernel(
    const float* __restrict__ Wkc, const float* __restrict__ Wvc)
{
    __shared__ float t[32][33];
    const int kb = blockIdx.x * 32;
    const int nb = blockIdx.y * 32;
    const float* W = (nb < NHD) ? Wkc : Wvc;
    const int nloc = (nb < NHD) ? nb : nb - NHD;
    const int tx = threadIdx.x & 31, ty = threadIdx.x >> 5;
    #pragma unroll
    for (int j = 0; j < 4; j++)
        t[ty + 8 * j][tx] = W[(size_t)(kb + ty + 8 * j) * NHD + nloc + tx];
    __syncthreads();
    #pragma unroll
    for (int j = 0; j < 4; j++)
        g_WTh[(size_t)(nb + ty + 8 * j) * GH + kb + tx] = __float2half_rn(t[tx][ty + 8 * j]);
}

// ---------------------------------------------------------------------------
// Kernel 1: fp16 GEMM (fp32 accum), epilogue stores fp16 to g_Ch
// ---------------------------------------------------------------------------
__global__ __launch_bounds__(128, 2) void gemm_mma_kernel()
{
    __shared__ __align__(16) uint32_t As[2][128][AWORDS];
    __shared__ __align__(16) uint32_t Bs[2][128][AWORDS];

    const int tid = threadIdx.x;
    const int bx = blockIdx.x;
    const int by = blockIdx.y;

    const int r0 = tid >> 2;
    const int ch = tid & 3;
    const __half* aS[4];
    const __half* bS[4];
    uint32_t aD[4], bD[4];
    #pragma unroll
    for (int j = 0; j < 4; j++) {
        aS[j] = g_Ah + (size_t)(by * 128 + r0 + 32 * j) * GH + ch * 8;
        bS[j] = g_WTh + (size_t)(bx * 128 + r0 + 32 * j) * GH + ch * 8;
        aD[j] = smem_u32(&As[0][r0 + 32 * j][ch * 4]);
        bD[j] = smem_u32(&Bs[0][r0 + 32 * j][ch * 4]);
    }
    const uint32_t stage_b = STAGE_W * 4;

    float acc[4][8][4];
    #pragma unroll
    for (int mi = 0; mi < 4; mi++)
        #pragma unroll
        for (int ni = 0; ni < 8; ni++)
            #pragma unroll
            for (int r = 0; r < 4; r++)
                acc[mi][ni][r] = 0.0f;

    const int lane = tid & 31;
    const int warp = tid >> 5;
    const int qp = lane >> 2;
    const int qc = lane & 3;
    const int wm = warp & 1;
    const int wn = warp >> 1;

    #pragma unroll
    for (int s = 0; s < 2; s++) {
        const int k0 = s * KC;
        const uint32_t so = s * stage_b;
        #pragma unroll
        for (int j = 0; j < 4; j++) {
            cp_async16(aD[j] + so, aS[j] + k0);
            cp_async16(bD[j] + so, bS[j] + k0);
        }
        cp_commit();
    }

    for (int it = 0; it < NITER; it++) {
        cp_wait1();
        __syncthreads();

        const int buf = it & 1;
        #pragma unroll
        for (int step = 0; step < 2; step++) {
            const int wb = step * 8;
            uint32_t a[4][4], b[8][2];
            #pragma unroll
            for (int mi = 0; mi < 4; mi++) {
                const int row = wm * 64 + mi * 16 + qp;
                a[mi][0] = As[buf][row][wb + qc];
                a[mi][1] = As[buf][row + 8][wb + qc];
                a[mi][2] = As[buf][row][wb + 4 + qc];
                a[mi][3] = As[buf][row + 8][wb + 4 + qc];
            }
            #pragma unroll
            for (int ni = 0; ni < 8; ni++) {
                const int rn = wn * 64 + ni * 8 + qp;
                b[ni][0] = Bs[buf][rn][wb + qc];
                b[ni][1] = Bs[buf][rn][wb + 4 + qc];
            }
            #pragma unroll
            for (int mi = 0; mi < 4; mi++)
                #pragma unroll
                for (int ni = 0; ni < 8; ni++)
                    mma_fp16(acc[mi][ni], a[mi], b[ni]);
        }

        __syncthreads();

        const int nxt = it + 2;
        if (nxt < NITER) {
            const int k0 = nxt * KC;
            const uint32_t so = (nxt & 1) * stage_b;
            #pragma unroll
            for (int j = 0; j < 4; j++) {
                cp_async16(aD[j] + so, aS[j] + k0);
                cp_async16(bD[j] + so, bS[j] + k0);
            }
        }
        cp_commit();
    }

    #pragma unroll
    for (int mi = 0; mi < 4; mi++) {
        const int row = by * 128 + wm * 64 + mi * 16 + qp;
        #pragma unroll
        for (int ni = 0; ni < 8; ni++) {
            const int col = bx * 128 + wn * 64 + ni * 8 + 2 * qc;
            *reinterpret_cast<__half2*>(&g_Ch[(size_t)row * KNN + col]) =
                __floats2half2_rn(acc[mi][ni][0], acc[mi][ni][1]);
            *reinterpret_cast<__half2*>(&g_Ch[(size_t)(row + 8) * KNN + col]) =
                __floats2half2_rn(acc[mi][ni][2], acc[mi][ni][3]);
        }
    }
}

// ---------------------------------------------------------------------------
// Kernel 2: tensor-core attention. Block = (b,n,h), 128 threads.
// Warps 0-3 load Q[16x128], K[32x128], V[32x128] (rows 20-31 zero) to fp16
// smem; warp 0 computes S = Q*K^T (mma), softmax (mask j>=20), O = P*V (mma,
// V B-fragments via ldmatrix.x4.trans).
// Row stride 136 halves (272 B) -> conflict-free fragment LDS + ldmatrix.
// ---------------------------------------------------------------------------
__global__ __launch_bounds__(128) void attn_kernel(
    const float* __restrict__ q,
    const float* __restrict__ k,
    const float* __restrict__ v,
    const int* __restrict__ mask,
    float* __restrict__ out)
{
    const int bid = blockIdx.x;
    const int h  = bid & 15;
    const int bn = bid >> 4;
    const int n  = bn & 255;
    const int b  = bn >> 8;

    __shared__ __half Qh[16][136];
    __shared__ __half Ks[32][136];
    __shared__ __half Vs[32][136];

    const int tid = threadIdx.x;
    const size_t qbase = ((size_t)(b * (GN * BSQ) + n * BSQ) * NH + h) * DH;
    const size_t cb = ((size_t)(b * GN + n) * GL) * KNN + (size_t)h * DH;

    // Loader: units of 4 elements. Q: 512, K: 1024, V: 1024.
    for (int u = tid; u < 2560; u += 128) {
        if (u < 512) {
            const int r = u >> 5, c4 = (u & 31) << 2;
            float4 x = *reinterpret_cast<const float4*>(&q[qbase + (size_t)r * NHD + c4]);
            __half2 h01 = __floats2half2_rn(x.x, x.y);
            __half2 h23 = __floats2half2_rn(x.z, x.w);
            uint32_t* d = reinterpret_cast<uint32_t*>(&Qh[r][c4]);
            d[0] = *reinterpret_cast<uint32_t*>(&h01);
            d[1] = *reinterpret_cast<uint32_t*>(&h23);
        } else {
            const int t = (u - 512) & 1023;
            const bool isV = (u >= 1536);
            const int j = t >> 5, c4 = (t & 31) << 2;
            uint32_t w0 = 0, w1 = 0;
            if (j < GL) {   // ctx rows from g_Ch (already fp16)
                const uint32_t* s = reinterpret_cast<const uint32_t*>(
                    &g_Ch[cb + (size_t)j * KNN + (isV ? NHD : 0) + c4]);
                w0 = s[0]; w1 = s[1];
            } else if (j < 20) {
                const float* src = isV ? v : k;
                float4 x = *reinterpret_cast<const float4*>(
                    &src[qbase + (size_t)(j - GL) * NHD + c4]);
                __half2 h01 = __floats2half2_rn(x.x, x.y);
                __half2 h23 = __floats2half2_rn(x.z, x.w);
                w0 = *reinterpret_cast<uint32_t*>(&h01);
                w1 = *reinterpret_cast<uint32_t*>(&h23);
            }
            uint32_t* d = isV ? reinterpret_cast<uint32_t*>(&Vs[j][c4])
                              : reinterpret_cast<uint32_t*>(&Ks[j][c4]);
            d[0] = w0; d[1] = w1;
        }
    }
    __syncthreads();

    if (tid >= 32) return;   // warp 0 computes

    const int lane = tid;
    const int qp = lane >> 2;
    const int qc = lane & 3;
    const float keep = (mask[b * GN + n] != 0) ? 1.0f : 0.0f;

    // ---- S = Q K^T : 4 n-tiles (j), 8 k-tiles (d) ----
    float sc[4][4];
    #pragma unroll
    for (int ni = 0; ni < 4; ni++)
        #pragma unroll
        for (int c = 0; c < 4; c++)
            sc[ni][c] = 0.0f;

    #pragma unroll
    for (int kt = 0; kt < 8; kt++) {
        const int d = kt * 16;
        uint32_t a[4];
        a[0] = *reinterpret_cast<const uint32_t*>(&Qh[qp][d + 2 * qc]);
        a[1] = *reinterpret_cast<const uint32_t*>(&Qh[qp + 8][d + 2 * qc]);
        a[2] = *reinterpret_cast<const uint32_t*>(&Qh[qp][d + 8 + 2 * qc]);
        a[3] = *reinterpret_cast<const uint32_t*>(&Qh[qp + 8][d + 8 + 2 * qc]);
        #pragma unroll
        for (int ni = 0; ni < 4; ni++) {
            uint32_t bfr[2];
            bfr[0] = *reinterpret_cast<const uint32_t*>(&Ks[ni * 8 + qp][d + 2 * qc]);
            bfr[1] = *reinterpret_cast<const uint32_t*>(&Ks[ni * 8 + qp][d + 8 + 2 * qc]);
            mma_fp16(sc[ni], a, bfr);
        }
    }

    // ---- scale + mask (j >= 20) ----
    #pragma unroll
    for (int ni = 0; ni < 4; ni++) {
        const int j0 = ni * 8 + 2 * qc;
        #pragma unroll
        for (int c = 0; c < 4; c++) {
            const int j = j0 + (c & 1);
            float s = sc[ni][c] * SCALE;
            if (j >= 20) s = -1e30f;
            sc[ni][c] = s;
        }
    }

    // ---- softmax rows qp (c0,c1) and qp+8 (c2,c3) ----
    float m0 = -1e30f, m1 = -1e30f;
    #pragma unroll
    for (int ni = 0; ni < 4; ni++) {
        m0 = fmaxf(m0, fmaxf(sc[ni][0], sc[ni][1]));
        m1 = fmaxf(m1, fmaxf(sc[ni][2], sc[ni][3]));
    }
    m0 = fmaxf(m0, __shfl_xor_sync(0xffffffff, m0, 1));
    m0 = fmaxf(m0, __shfl_xor_sync(0xffffffff, m0, 2));
    m1 = fmaxf(m1, __shfl_xor_sync(0xffffffff, m1, 1));
    m1 = fmaxf(m1, __shfl_xor_sync(0xffffffff, m1, 2));

    float s0 = 0.0f, s1 = 0.0f;
    #pragma unroll
    for (int ni = 0; ni < 4; ni++) {
        sc[ni][0] = __expf(sc[ni][0] - m0); s0 += sc[ni][0];
        sc[ni][1] = __expf(sc[ni][1] - m0); s0 += sc[ni][1];
        sc[ni][2] = __expf(sc[ni][2] - m1); s1 += sc[ni][2];
        sc[ni][3] = __expf(sc[ni][3] - m1); s1 += sc[ni][3];
    }
    s0 += __shfl_xor_sync(0xffffffff, s0, 1);
    s0 += __shfl_xor_sync(0xffffffff, s0, 2);
    s1 += __shfl_xor_sync(0xffffffff, s1, 1);
    s1 += __shfl_xor_sync(0xffffffff, s1, 2);
    const float inv0 = keep / s0;
    const float inv1 = keep / s1;

    // ---- pack P into A fragments: pA[kt] covers k = j in [kt*16, kt*16+16) ----
    uint32_t pA[2][4];
    #pragma unroll
    for (int kt = 0; kt < 2; kt++) {
        __half2 t0 = __floats2half2_rn(sc[2 * kt][0], sc[2 * kt][1]);
        __half2 t1 = __floats2half2_rn(sc[2 * kt][2], sc[2 * kt][3]);
        __half2 t2 = __floats2half2_rn(sc[2 * kt + 1][0], sc[2 * kt + 1][1]);
        __half2 t3 = __floats2half2_rn(sc[2 * kt + 1][2], sc[2 * kt + 1][3]);
        pA[kt][0] = *reinterpret_cast<uint32_t*>(&t0);
        pA[kt][1] = *reinterpret_cast<uint32_t*>(&t1);
        pA[kt][2] = *reinterpret_cast<uint32_t*>(&t2);
        pA[kt][3] = *reinterpret_cast<uint32_t*>(&t3);
    }

    // ---- O = P V : per 16-col slab, B via ldmatrix.x4.trans ----
    const uint32_t vsb = smem_u32(&Vs[0][0]);
    const int lrow = lane & 15;
    const int lchunk = (lane >> 4) << 3;
    const size_t ob0 = ((size_t)(b * (GN * BSQ) + n * BSQ + qp)) * NHD + (size_t)h * DH;
    const size_t ob1 = ob0 + (size_t)8 * NHD;

    #pragma unroll
    for (int d0 = 0; d0 < 128; d0 += 16) {
        float o[2][4];
        #pragma unroll
        for (int t = 0; t < 2; t++)
            #pragma unroll
            for (int c = 0; c < 4; c++)
                o[t][c] = 0.0f;
        #pragma unroll
        for (int kt = 0; kt < 2; kt++) {
            uint32_t r0, r1, r2, r3;
            const uint32_t addr = vsb + (uint32_t)((kt * 16 + lrow) * 272 + (d0 + lchunk) * 2);
            ldsm_x4_t(r0, r1, r2, r3, addr);
            uint32_t b0[2] = { r0, r1 };
            uint32_t b1[2] = { r2, r3 };
            mma_fp16(o[0], pA[kt], b0);
            mma_fp16(o[1], pA[kt], b1);
        }
        #pragma unroll
        for (int t = 0; t < 2; t++) {
            const int col = d0 + t * 8 + 2 * qc;
            *reinterpret_cast<float2*>(&out[ob0 + col]) =
                make_float2(o[t][0] * inv0, o[t][1] * inv0);
            *reinterpret_cast<float2*>(&out[ob1 + col]) =
                make_float2(o[t][2] * inv1, o[t][3] * inv1);
        }
    }
}

// ---------------------------------------------------------------------------
// kernel_launch
// ---------------------------------------------------------------------------
extern "C" void kernel_launch(void* const* d_in, const int* in_sizes, int n_in,
                              void* d_out, int out_size)
{
    const float* hidden = (const float*)d_in[0];
    const void*  anchor = d_in[1];
    const int*   mask   = (const int*)d_in[2];
    const float* q      = (const float*)d_in[3];
    const float* k      = (const float*)d_in[4];
    const float* v      = (const float*)d_in[5];
    const float* Wkc    = (const float*)d_in[6];
    const float* Wvc    = (const float*)d_in[7];

    gather_a_kernel<<<MM, 256>>>(hidden, anchor);

    dim3 tgrid(GH / 32, KNN / 32);   // (64, 128)
    transpose_w_kernel<<<tgrid, 256>>>(Wkc, Wvc);

    dim3 ggrid(KNN / 128, MM / 128); // (32, 16)
    gemm_mma_kernel<<<ggrid, 128>>>();

    attn_kernel<<<GB * GN * NH, 128>>>(q, k, v, mask, (float*)d_out);
}